// round 2
// baseline (speedup 1.0000x reference)
#include <cuda_runtime.h>
#include <cstring>

// Problem (fixed by dataset): B=4, N=2048, Fin=128, H=4, Fout=32.
// Identity: softmax(scores, m).sum(m) == 1  =>  out = (1+self_weight)*(x @ W).
// adj and att are dead inputs.
//
// fp32 SGEMM [M=8192,K=128] @ [K=128,N=128] via packed fma.rn.f32x2.
// R2: KB=64 (2 sync pairs instead of 8), xs padded to kill the 2-way
// bank conflict on x smem reads.

#define KDIM 128
#define NDIM 128
#define TM 64      // rows per block
#define TN 64      // cols per block
#define KB 64      // K chunk staged in smem
#define XPAD 4     // xs row padding (floats): keeps 16B align, offsets banks

__device__ __forceinline__ void fma2(unsigned long long& d,
                                     unsigned long long a,
                                     unsigned long long b) {
    asm("fma.rn.f32x2 %0, %1, %2, %0;" : "+l"(d) : "l"(a), "l"(b));
}

__device__ __forceinline__ unsigned long long dup2(float x) {
    unsigned long long r;
    asm("mov.b64 %0, {%1, %1};" : "=l"(r) : "f"(x));
    return r;
}

__global__ __launch_bounds__(256, 2)
void gat_gemm_kernel(const float* __restrict__ x,
                     const float* __restrict__ W,
                     const float* __restrict__ self_weight,
                     float* __restrict__ out) {
    __shared__ float xs[TM][KB + XPAD];  // 64 x 68 floats = 17408 B
    __shared__ float ws[KB][TN];         // 64 x 64 floats = 16384 B

    const int tid  = threadIdx.x;
    const int bcol = blockIdx.x & 1;        // 2 column tiles (128/64)
    const int brow = blockIdx.x >> 1;       // 128 row tiles  (8192/64)
    const int row0 = brow * TM;
    const int col0 = bcol * TN;

    // thread -> 4 rows x 4 cols of the 64x64 tile
    const int cx = tid & 15;                // col quad: cols cx*4 .. cx*4+3
    const int ry = tid >> 4;                // row quad: rows ry*4 .. ry*4+3

    unsigned long long acc[4][2];
    #pragma unroll
    for (int i = 0; i < 4; i++) { acc[i][0] = 0ull; acc[i][1] = 0ull; }

    #pragma unroll
    for (int kb = 0; kb < KDIM; kb += KB) {
        // ---- stage: xs 64x64 floats (1024 float4), ws 64x64 (1024 float4) ----
        #pragma unroll
        for (int rep = 0; rep < 4; rep++) {
            int s  = tid + rep * 256;
            int xr = s >> 4, xq = s & 15;   // 16 float4 per 64-float row
            *(float4*)&xs[xr][xq * 4] =
                *(const float4*)&x[(size_t)(row0 + xr) * KDIM + kb + xq * 4];
            int wr = s >> 4, wq = s & 15;
            *(float4*)&ws[wr][wq * 4] =
                *(const float4*)&W[(size_t)(kb + wr) * NDIM + col0 + wq * 4];
        }
        __syncthreads();

        // ---- compute: 64 k-steps, fully unrolled in 4-k groups ----
        #pragma unroll
        for (int k4 = 0; k4 < KB; k4 += 4) {
            float4 xq[4];
            #pragma unroll
            for (int i = 0; i < 4; i++)
                xq[i] = *(const float4*)&xs[ry * 4 + i][k4];

            #pragma unroll
            for (int kk = 0; kk < 4; kk++) {
                ulonglong2 w2 = *(const ulonglong2*)&ws[k4 + kk][cx * 4];
                #pragma unroll
                for (int i = 0; i < 4; i++) {
                    float xv = (kk == 0) ? xq[i].x :
                               (kk == 1) ? xq[i].y :
                               (kk == 2) ? xq[i].z : xq[i].w;
                    unsigned long long x2 = dup2(xv);
                    fma2(acc[i][0], x2, w2.x);
                    fma2(acc[i][1], x2, w2.y);
                }
            }
        }
        __syncthreads();
    }

    // ---- epilogue: scale by (1 + self_weight) and store ----
    const float scale = 1.0f + self_weight[0];
    #pragma unroll
    for (int i = 0; i < 4; i++) {
        float2 a0, a1;
        memcpy(&a0, &acc[i][0], 8);
        memcpy(&a1, &acc[i][1], 8);
        float4 o;
        o.x = a0.x * scale; o.y = a0.y * scale;
        o.z = a1.x * scale; o.w = a1.y * scale;
        *(float4*)&out[(size_t)(row0 + ry * 4 + i) * NDIM + col0 + cx * 4] = o;
    }
}

extern "C" void kernel_launch(void* const* d_in, const int* in_sizes, int n_in,
                              void* d_out, int out_size) {
    // metadata order: x (f32), adj (i32, UNUSED), W (f32), att (f32, UNUSED),
    //                 self_weight (f32)
    const float* x  = (const float*)d_in[0];
    const float* W  = (const float*)d_in[2];
    const float* sw = (const float*)d_in[4];
    float* out      = (float*)d_out;

    const int M = in_sizes[0] / KDIM;          // 8192
    dim3 grid((M / TM) * (NDIM / TN));         // 128 * 2 = 256 blocks
    gat_gemm_kernel<<<grid, 256>>>(x, W, sw, out);
}

// round 4
// speedup vs baseline: 1.2554x; 1.2554x over previous
#include <cuda_runtime.h>
#include <cuda_bf16.h>
#include <cstdint>

// Problem (fixed): B=4,N=2048,Fin=128,H=4,Fout=32.
// Identity: softmax(scores,m).sum(m)==1  =>  out = (1+self_weight)*(x @ W).
// adj, att are dead inputs.
//
// R4: mma.sync bf16 (HMMA, base-target sm_103 -- tcgen05 is 'a'-gated and the
// harness PTX targets plain sm_103). 3-term precision split:
//   x = xh + xl (bf16), W = wh + wl (bf16)
//   out ~= xh*wh + xh*wl + xl*wh   (fp32 accumulate; rel err ~1e-5)
// Block: 128 rows x 64 cols, K=128 resident. Grid = 64*2 = 128 (one wave).

#define KDIM 128
#define NDIM 128
#define TM 128
#define TN 64
#define ASTRIDE 272   // smem row stride bytes (256 data + 16 pad): bank-clean

#define SMEM_AH 0
#define SMEM_AL (SMEM_AH + TM * ASTRIDE)      // 34816
#define SMEM_BH (SMEM_AL + TM * ASTRIDE)      // 69632
#define SMEM_BL (SMEM_BH + TN * ASTRIDE)      // 87040
#define SMEM_TOTAL (SMEM_BL + TN * ASTRIDE)   // 104448

__device__ __forceinline__ uint32_t smem_u32(const void* p) {
    uint32_t a;
    asm("{ .reg .u64 t; cvta.to.shared.u64 t, %1; cvt.u32.u64 %0, t; }"
        : "=r"(a) : "l"(p));
    return a;
}

__device__ __forceinline__ void ldsm4(uint32_t r[4], uint32_t addr) {
    asm volatile("ldmatrix.sync.aligned.m8n8.x4.shared.b16 {%0,%1,%2,%3}, [%4];"
                 : "=r"(r[0]), "=r"(r[1]), "=r"(r[2]), "=r"(r[3]) : "r"(addr));
}

__device__ __forceinline__ void mma_bf16(float c[4], const uint32_t a[4],
                                         uint32_t b0, uint32_t b1) {
    asm volatile(
        "mma.sync.aligned.m16n8k16.row.col.f32.bf16.bf16.f32 "
        "{%0,%1,%2,%3}, {%4,%5,%6,%7}, {%8,%9}, {%0,%1,%2,%3};"
        : "+f"(c[0]), "+f"(c[1]), "+f"(c[2]), "+f"(c[3])
        : "r"(a[0]), "r"(a[1]), "r"(a[2]), "r"(a[3]), "r"(b0), "r"(b1));
}

// split a float4 into packed-bf16x4 hi and lo halves (8B each)
__device__ __forceinline__ void split4(const float4& f,
                                       unsigned long long& hp,
                                       unsigned long long& lp) {
    float v[4] = {f.x, f.y, f.z, f.w};
    unsigned long long h = 0, l = 0;
    #pragma unroll
    for (int i = 0; i < 4; i++) {
        __nv_bfloat16 hb = __float2bfloat16_rn(v[i]);
        float r = v[i] - __bfloat162float(hb);
        __nv_bfloat16 lb = __float2bfloat16_rn(r);
        h |= (unsigned long long)__bfloat16_as_ushort(hb) << (16 * i);
        l |= (unsigned long long)__bfloat16_as_ushort(lb) << (16 * i);
    }
    hp = h; lp = l;
}

__global__ __launch_bounds__(256, 1)
void gat_hmma_kernel(const float* __restrict__ x,
                     const float* __restrict__ W,
                     const float* __restrict__ self_weight,
                     float* __restrict__ out) {
    extern __shared__ char smem[];
    const uint32_t sbase = smem_u32(smem);
    const int tid = threadIdx.x;
    const int wid = tid >> 5;
    const int lid = tid & 31;

    const int bcol = blockIdx.x & 1;
    const int brow = blockIdx.x >> 1;
    const int row0 = brow * TM;
    const int col0 = bcol * TN;

    // ---- stage A: x[row0..+127][0..127] fp32 -> bf16 hi/lo in smem ----
    #pragma unroll
    for (int r = 0; r < 16; r++) {
        int g = tid + r * 256;
        int m = g >> 5;                 // 0..127
        int k = (g & 31) << 2;          // 0..124 step 4
        float4 f = *(const float4*)&x[(size_t)(row0 + m) * KDIM + k];
        unsigned long long hp, lp;
        split4(f, hp, lp);
        *(unsigned long long*)(smem + SMEM_AH + m * ASTRIDE + k * 2) = hp;
        *(unsigned long long*)(smem + SMEM_AL + m * ASTRIDE + k * 2) = lp;
    }

    // ---- stage B: Bt[n][k] = W[k][col0+n], n in [0,64) ----
    {
        int n  = tid & 63;
        int kq = tid >> 6;              // 0..3
        #pragma unroll
        for (int r = 0; r < 8; r++) {
            int k = (kq + r * 4) << 2;  // 0..124 step 4 across (kq,r)
            float4 f;
            f.x = W[(size_t)(k + 0) * NDIM + col0 + n];
            f.y = W[(size_t)(k + 1) * NDIM + col0 + n];
            f.z = W[(size_t)(k + 2) * NDIM + col0 + n];
            f.w = W[(size_t)(k + 3) * NDIM + col0 + n];
            unsigned long long hp, lp;
            split4(f, hp, lp);
            *(unsigned long long*)(smem + SMEM_BH + n * ASTRIDE + k * 2) = hp;
            *(unsigned long long*)(smem + SMEM_BL + n * ASTRIDE + k * 2) = lp;
        }
    }
    __syncthreads();

    // ---- compute: warp tile 32 rows x 32 cols ----
    const int wm = (wid >> 1) * 32;     // 0,32,64,96
    const int wn = (wid & 1) * 32;      // 0,32

    float acc[2][4][4];                 // [m-tile][n-tile][frag]
    #pragma unroll
    for (int i = 0; i < 2; i++)
        #pragma unroll
        for (int j = 0; j < 4; j++)
            #pragma unroll
            for (int e = 0; e < 4; e++) acc[i][j][e] = 0.0f;

    // per-lane ldmatrix base addresses (k-step adds 32 bytes each)
    // A (x4): lanes 0-15 rows 0..15 @klo, lanes 16-31 rows 0..15 @khi
    uint32_t aAddr[2];
    #pragma unroll
    for (int mt = 0; mt < 2; mt++)
        aAddr[mt] = sbase + SMEM_AH
                  + (wm + 16 * mt + (lid & 15)) * ASTRIDE + 16 * (lid >> 4);
    // B (x4): covers n-tile pair; lanes 0-7 n0..7@klo, 8-15 n0..7@khi,
    //         16-23 n8..15@klo, 24-31 n8..15@khi
    uint32_t bAddr[2];
    #pragma unroll
    for (int p = 0; p < 2; p++)
        bAddr[p] = sbase + SMEM_BH
                 + (wn + 16 * p + (lid & 7) + 8 * (lid >> 4)) * ASTRIDE
                 + 16 * ((lid >> 3) & 1);

    const uint32_t dAL = SMEM_AL - SMEM_AH;   // hi -> lo buffer delta
    const uint32_t dBL = SMEM_BL - SMEM_BH;

    #pragma unroll
    for (int ks = 0; ks < 8; ks++) {
        const uint32_t ko = ks * 32;    // 16 bf16 = 32 bytes per k-step

        uint32_t ah[2][4], al[2][4];
        #pragma unroll
        for (int mt = 0; mt < 2; mt++) {
            ldsm4(ah[mt], aAddr[mt] + ko);
            ldsm4(al[mt], aAddr[mt] + ko + dAL);
        }
        uint32_t bh[2][4], bl[2][4];    // [pair][4]: regs {t0b0,t0b1,t1b0,t1b1}
        #pragma unroll
        for (int p = 0; p < 2; p++) {
            ldsm4(bh[p], bAddr[p] + ko);
            ldsm4(bl[p], bAddr[p] + ko + dBL);
        }

        #pragma unroll
        for (int mt = 0; mt < 2; mt++) {
            #pragma unroll
            for (int nt = 0; nt < 4; nt++) {
                const int p = nt >> 1, q = (nt & 1) * 2;
                mma_bf16(acc[mt][nt], ah[mt], bh[p][q], bh[p][q + 1]); // hh
                mma_bf16(acc[mt][nt], ah[mt], bl[p][q], bl[p][q + 1]); // hl
                mma_bf16(acc[mt][nt], al[mt], bh[p][q], bh[p][q + 1]); // lh
            }
        }
    }

    // ---- epilogue: scale and store ----
    const float s = 1.0f + self_weight[0];
    #pragma unroll
    for (int mt = 0; mt < 2; mt++) {
        #pragma unroll
        for (int nt = 0; nt < 4; nt++) {
            const int r0 = row0 + wm + 16 * mt + (lid >> 2);
            const int c  = col0 + wn + 8 * nt + 2 * (lid & 3);
            float2 s0 = {acc[mt][nt][0] * s, acc[mt][nt][1] * s};
            float2 s1 = {acc[mt][nt][2] * s, acc[mt][nt][3] * s};
            *(float2*)&out[(size_t)r0 * NDIM + c]       = s0;
            *(float2*)&out[(size_t)(r0 + 8) * NDIM + c] = s1;
        }
    }
}

extern "C" void kernel_launch(void* const* d_in, const int* in_sizes, int n_in,
                              void* d_out, int out_size) {
    // metadata order: x, adj (UNUSED), W, att (UNUSED), self_weight
    const float* x  = (const float*)d_in[0];
    const float* W  = (const float*)d_in[2];
    const float* sw = (const float*)d_in[4];
    float* out      = (float*)d_out;

    cudaFuncSetAttribute(gat_hmma_kernel,
                         cudaFuncAttributeMaxDynamicSharedMemorySize, SMEM_TOTAL);

    const int M = in_sizes[0] / KDIM;             // 8192
    dim3 grid((M / TM) * (NDIM / TN));            // 64 * 2 = 128 blocks
    gat_hmma_kernel<<<grid, 256, SMEM_TOTAL>>>(x, W, sw, out);
}

// round 5
// speedup vs baseline: 1.4624x; 1.1649x over previous
#include <cuda_runtime.h>
#include <cuda_bf16.h>
#include <cstdint>

// Problem (fixed): B=4,N=2048,Fin=128,H=4,Fout=32.
// Identity: softmax(scores,m).sum(m)==1  =>  out = (1+self_weight)*(x @ W).
// adj, att are dead inputs.
//
// R5: HMMA bf16 3-term split (xh*wh + xh*wl + xl*wh, fp32 accum).
//  - occ 2 (TM=64, grid=256, <=128 regs) for cross-block latency overlap
//  - truncation-based split: PRMT for hi, LOP3+FSUB+cvt.bf16x2 for lo
//  - B kept k-major ([k][n], coalesced stage) + ldmatrix.x4.trans

#define KDIM 128
#define NDIM 128
#define TM 64
#define TN 64
#define ASTRIDE 272   // A row: 128 bf16 = 256B data + 16 pad (4-bank shift)
#define BSTRIDE 144   // B row: 64 bf16 = 128B data + 16 pad (4-bank shift)

#define SMEM_AH 0
#define SMEM_AL (SMEM_AH + TM * ASTRIDE)        // 17408
#define SMEM_BH (SMEM_AL + TM * ASTRIDE)        // 34816
#define SMEM_BL (SMEM_BH + KDIM * BSTRIDE)      // 53248
#define SMEM_TOTAL (SMEM_BL + KDIM * BSTRIDE)   // 71680

__device__ __forceinline__ uint32_t smem_u32(const void* p) {
    uint32_t a;
    asm("{ .reg .u64 t; cvta.to.shared.u64 t, %1; cvt.u32.u64 %0, t; }"
        : "=r"(a) : "l"(p));
    return a;
}

__device__ __forceinline__ void ldsm4(uint32_t r[4], uint32_t addr) {
    asm volatile("ldmatrix.sync.aligned.m8n8.x4.shared.b16 {%0,%1,%2,%3}, [%4];"
                 : "=r"(r[0]), "=r"(r[1]), "=r"(r[2]), "=r"(r[3]) : "r"(addr));
}
__device__ __forceinline__ void ldsm4t(uint32_t r[4], uint32_t addr) {
    asm volatile("ldmatrix.sync.aligned.m8n8.x4.trans.shared.b16 {%0,%1,%2,%3}, [%4];"
                 : "=r"(r[0]), "=r"(r[1]), "=r"(r[2]), "=r"(r[3]) : "r"(addr));
}

__device__ __forceinline__ void mma_bf16(float c[4], const uint32_t a[4],
                                         uint32_t b0, uint32_t b1) {
    asm volatile(
        "mma.sync.aligned.m16n8k16.row.col.f32.bf16.bf16.f32 "
        "{%0,%1,%2,%3}, {%4,%5,%6,%7}, {%8,%9}, {%0,%1,%2,%3};"
        : "+f"(c[0]), "+f"(c[1]), "+f"(c[2]), "+f"(c[3])
        : "r"(a[0]), "r"(a[1]), "r"(a[2]), "r"(a[3]), "r"(b0), "r"(b1));
}

// split two floats: hi = truncated-bf16 pair (a->low), lo = rn-bf16 of residual
__device__ __forceinline__ void split2(float a, float b,
                                       uint32_t& hi, uint32_t& lo) {
    uint32_t ua = __float_as_uint(a), ub = __float_as_uint(b);
    asm("prmt.b32 %0, %1, %2, 0x7632;" : "=r"(hi) : "r"(ua), "r"(ub));
    float ra = a - __uint_as_float(ua & 0xFFFF0000u);
    float rb = b - __uint_as_float(ub & 0xFFFF0000u);
    asm("cvt.rn.bf16x2.f32 %0, %1, %2;" : "=r"(lo) : "f"(rb), "f"(ra));
}
__device__ __forceinline__ void split4(const float4& f, uint2& hp, uint2& lp) {
    split2(f.x, f.y, hp.x, lp.x);
    split2(f.z, f.w, hp.y, lp.y);
}

__global__ __launch_bounds__(256, 2)
void gat_hmma_kernel(const float* __restrict__ x,
                     const float* __restrict__ W,
                     const float* __restrict__ self_weight,
                     float* __restrict__ out) {
    extern __shared__ char smem[];
    const uint32_t sbase = smem_u32(smem);
    const int tid = threadIdx.x;
    const int wid = tid >> 5;
    const int lid = tid & 31;

    const int bcol = blockIdx.x & 1;
    const int brow = blockIdx.x >> 1;
    const int row0 = brow * TM;
    const int col0 = bcol * TN;

    const float s = 1.0f + self_weight[0];   // hoisted before barrier

    // ---- stage A: x[row0..+63][0..127] -> bf16 hi/lo smem, row-major ----
    #pragma unroll
    for (int r = 0; r < 8; r++) {
        int g  = tid + r * 256;      // 0..2047
        int m  = g >> 5;             // 0..63
        int k4 = g & 31;             // float4 index in row
        float4 f = *(const float4*)&x[(size_t)(row0 + m) * KDIM + k4 * 4];
        uint2 hp, lp;
        split4(f, hp, lp);
        *(uint2*)(smem + SMEM_AH + m * ASTRIDE + k4 * 8) = hp;
        *(uint2*)(smem + SMEM_AL + m * ASTRIDE + k4 * 8) = lp;
    }

    // ---- stage B: W[k][col0..+63] -> bf16 hi/lo smem, k-major (coalesced) ----
    #pragma unroll
    for (int r = 0; r < 8; r++) {
        int g  = tid + r * 256;      // 0..2047
        int k  = g >> 4;             // 0..127
        int n4 = g & 15;             // float4 index in 64-col row
        float4 f = *(const float4*)&W[(size_t)k * NDIM + col0 + n4 * 4];
        uint2 hp, lp;
        split4(f, hp, lp);
        *(uint2*)(smem + SMEM_BH + k * BSTRIDE + n4 * 8) = hp;
        *(uint2*)(smem + SMEM_BL + k * BSTRIDE + n4 * 8) = lp;
    }
    __syncthreads();

    // ---- compute: warp tile 16 rows x 32 cols (4x2 warp grid) ----
    const int wm = (wid >> 1) * 16;     // 0,16,32,48
    const int wn = (wid & 1) * 32;      // 0,32

    float acc[4][4];                    // [n-tile][frag]
    #pragma unroll
    for (int j = 0; j < 4; j++)
        #pragma unroll
        for (int e = 0; e < 4; e++) acc[j][e] = 0.0f;

    // A x4 (non-trans) from [m][k]: groups m0-7@k0, m8-15@k0, m0-7@k8, m8-15@k8
    const uint32_t aAddr = sbase + SMEM_AH
        + (wm + (lid & 15)) * ASTRIDE + 16 * (lid >> 4);
    // B x4 trans from [k][n]: groups k0-7@n0, k8-15@n0, k0-7@n8, k8-15@n8
    // lane l: k-row = 8*((l>>3)&1) + (l&7); n-col byte = (wn + 8*(l>>4))*2
    uint32_t bAddr[2];
    #pragma unroll
    for (int p = 0; p < 2; p++)
        bAddr[p] = sbase + SMEM_BH
            + (8 * ((lid >> 3) & 1) + (lid & 7)) * BSTRIDE
            + (wn + 16 * p + 8 * (lid >> 4)) * 2;

    const uint32_t dAL = SMEM_AL - SMEM_AH;
    const uint32_t dBL = SMEM_BL - SMEM_BH;

    #pragma unroll
    for (int ks = 0; ks < 8; ks++) {
        const uint32_t ako = ks * 32;            // 16 bf16 = 32B along A row
        const uint32_t bko = ks * 16 * BSTRIDE;  // 16 k-rows down B tile

        uint32_t ah[4], al[4];
        ldsm4(ah, aAddr + ako);
        ldsm4(al, aAddr + ako + dAL);

        uint32_t bh[2][4], bl[2][4];  // [n16-pair][{n0-7k0-7,n0-7k8-15,n8-15k0-7,n8-15k8-15}]
        #pragma unroll
        for (int p = 0; p < 2; p++) {
            ldsm4t(bh[p], bAddr[p] + bko);
            ldsm4t(bl[p], bAddr[p] + bko + dBL);
        }

        #pragma unroll
        for (int nt = 0; nt < 4; nt++) {
            const int p = nt >> 1, q = (nt & 1) * 2;
            mma_bf16(acc[nt], ah, bh[p][q], bh[p][q + 1]); // hh
            mma_bf16(acc[nt], ah, bl[p][q], bl[p][q + 1]); // hl
            mma_bf16(acc[nt], al, bh[p][q], bh[p][q + 1]); // lh
        }
    }

    // ---- epilogue: scale and store ----
    #pragma unroll
    for (int nt = 0; nt < 4; nt++) {
        const int r0 = row0 + wm + (lid >> 2);
        const int c  = col0 + wn + 8 * nt + 2 * (lid & 3);
        float2 s0 = {acc[nt][0] * s, acc[nt][1] * s};
        float2 s1 = {acc[nt][2] * s, acc[nt][3] * s};
        *(float2*)&out[(size_t)r0 * NDIM + c]       = s0;
        *(float2*)&out[(size_t)(r0 + 8) * NDIM + c] = s1;
    }
}

extern "C" void kernel_launch(void* const* d_in, const int* in_sizes, int n_in,
                              void* d_out, int out_size) {
    // metadata order: x, adj (UNUSED), W, att (UNUSED), self_weight
    const float* x  = (const float*)d_in[0];
    const float* W  = (const float*)d_in[2];
    const float* sw = (const float*)d_in[4];
    float* out      = (float*)d_out;

    cudaFuncSetAttribute(gat_hmma_kernel,
                         cudaFuncAttributeMaxDynamicSharedMemorySize, SMEM_TOTAL);

    const int M = in_sizes[0] / KDIM;             // 8192
    dim3 grid((M / TM) * (NDIM / TN));            // 128 * 2 = 256 blocks
    gat_hmma_kernel<<<grid, 256, SMEM_TOTAL>>>(x, W, sw, out);
}

// round 6
// speedup vs baseline: 1.5055x; 1.0295x over previous
#include <cuda_runtime.h>
#include <cuda_bf16.h>
#include <cstdint>

// Problem (fixed): B=4,N=2048,Fin=128,H=4,Fout=32.
// Identity: softmax(scores,m).sum(m)==1  =>  out = (1+self_weight)*(x @ W).
// adj, att are dead inputs.
//
// R6: HMMA bf16 3-term split with
//  - SEPARATE accumulators per term (hh/hl/lh): 12 independent 8-deep MMA
//    chains per warp (was 4 x 24-deep)
//  - all 16 LDG.128 batched before any convert (MLP=16 staging)

#define KDIM 128
#define NDIM 128
#define TM 64
#define TN 64
#define ASTRIDE 272   // A row: 128 bf16 = 256B data + 16 pad
#define BSTRIDE 144   // B row: 64 bf16 = 128B data + 16 pad

#define SMEM_AH 0
#define SMEM_AL (SMEM_AH + TM * ASTRIDE)        // 17408
#define SMEM_BH (SMEM_AL + TM * ASTRIDE)        // 34816
#define SMEM_BL (SMEM_BH + KDIM * BSTRIDE)      // 53248
#define SMEM_TOTAL (SMEM_BL + KDIM * BSTRIDE)   // 71680

__device__ __forceinline__ uint32_t smem_u32(const void* p) {
    uint32_t a;
    asm("{ .reg .u64 t; cvta.to.shared.u64 t, %1; cvt.u32.u64 %0, t; }"
        : "=r"(a) : "l"(p));
    return a;
}

__device__ __forceinline__ void ldsm4(uint32_t r[4], uint32_t addr) {
    asm volatile("ldmatrix.sync.aligned.m8n8.x4.shared.b16 {%0,%1,%2,%3}, [%4];"
                 : "=r"(r[0]), "=r"(r[1]), "=r"(r[2]), "=r"(r[3]) : "r"(addr));
}
__device__ __forceinline__ void ldsm4t(uint32_t r[4], uint32_t addr) {
    asm volatile("ldmatrix.sync.aligned.m8n8.x4.trans.shared.b16 {%0,%1,%2,%3}, [%4];"
                 : "=r"(r[0]), "=r"(r[1]), "=r"(r[2]), "=r"(r[3]) : "r"(addr));
}

__device__ __forceinline__ void mma_bf16(float c[4], const uint32_t a[4],
                                         uint32_t b0, uint32_t b1) {
    asm volatile(
        "mma.sync.aligned.m16n8k16.row.col.f32.bf16.bf16.f32 "
        "{%0,%1,%2,%3}, {%4,%5,%6,%7}, {%8,%9}, {%0,%1,%2,%3};"
        : "+f"(c[0]), "+f"(c[1]), "+f"(c[2]), "+f"(c[3])
        : "r"(a[0]), "r"(a[1]), "r"(a[2]), "r"(a[3]), "r"(b0), "r"(b1));
}

// split two floats: hi = truncated-bf16 pair, lo = rn-bf16 of residual
__device__ __forceinline__ void split2(float a, float b,
                                       uint32_t& hi, uint32_t& lo) {
    uint32_t ua = __float_as_uint(a), ub = __float_as_uint(b);
    asm("prmt.b32 %0, %1, %2, 0x7632;" : "=r"(hi) : "r"(ua), "r"(ub));
    float ra = a - __uint_as_float(ua & 0xFFFF0000u);
    float rb = b - __uint_as_float(ub & 0xFFFF0000u);
    asm("cvt.rn.bf16x2.f32 %0, %1, %2;" : "=r"(lo) : "f"(rb), "f"(ra));
}
__device__ __forceinline__ void split4(const float4& f, uint2& hp, uint2& lp) {
    split2(f.x, f.y, hp.x, lp.x);
    split2(f.z, f.w, hp.y, lp.y);
}

__global__ __launch_bounds__(256, 2)
void gat_hmma_kernel(const float* __restrict__ x,
                     const float* __restrict__ W,
                     const float* __restrict__ self_weight,
                     float* __restrict__ out) {
    extern __shared__ char smem[];
    const uint32_t sbase = smem_u32(smem);
    const int tid = threadIdx.x;
    const int wid = tid >> 5;
    const int lid = tid & 31;

    const int bcol = blockIdx.x & 1;
    const int brow = blockIdx.x >> 1;
    const int row0 = brow * TM;
    const int col0 = bcol * TN;

    const float s = 1.0f + self_weight[0];

    // ---- batched loads: all 16 LDG.128 in flight before any convert ----
    float4 fa[8], fb[8];
    #pragma unroll
    for (int r = 0; r < 8; r++) {
        int g  = tid + r * 256;
        int m  = g >> 5;                  // 0..63
        int k4 = g & 31;
        fa[r] = *(const float4*)&x[(size_t)(row0 + m) * KDIM + k4 * 4];
    }
    #pragma unroll
    for (int r = 0; r < 8; r++) {
        int g  = tid + r * 256;
        int k  = g >> 4;                  // 0..127
        int n4 = g & 15;
        fb[r] = *(const float4*)&W[(size_t)k * NDIM + col0 + n4 * 4];
    }

    // ---- convert + store A ----
    #pragma unroll
    for (int r = 0; r < 8; r++) {
        int g  = tid + r * 256;
        int m  = g >> 5;
        int k4 = g & 31;
        uint2 hp, lp;
        split4(fa[r], hp, lp);
        *(uint2*)(smem + SMEM_AH + m * ASTRIDE + k4 * 8) = hp;
        *(uint2*)(smem + SMEM_AL + m * ASTRIDE + k4 * 8) = lp;
    }
    // ---- convert + store B ----
    #pragma unroll
    for (int r = 0; r < 8; r++) {
        int g  = tid + r * 256;
        int k  = g >> 4;
        int n4 = g & 15;
        uint2 hp, lp;
        split4(fb[r], hp, lp);
        *(uint2*)(smem + SMEM_BH + k * BSTRIDE + n4 * 8) = hp;
        *(uint2*)(smem + SMEM_BL + k * BSTRIDE + n4 * 8) = lp;
    }
    __syncthreads();

    // ---- compute: warp tile 16 rows x 32 cols (4x2 warp grid) ----
    const int wm = (wid >> 1) * 16;     // 0,16,32,48
    const int wn = (wid & 1) * 32;      // 0,32

    float hh[4][4], hl[4][4], lh[4][4];
    #pragma unroll
    for (int j = 0; j < 4; j++)
        #pragma unroll
        for (int e = 0; e < 4; e++) { hh[j][e] = 0.f; hl[j][e] = 0.f; lh[j][e] = 0.f; }

    const uint32_t aAddr = sbase + SMEM_AH
        + (wm + (lid & 15)) * ASTRIDE + 16 * (lid >> 4);
    uint32_t bAddr[2];
    #pragma unroll
    for (int p = 0; p < 2; p++)
        bAddr[p] = sbase + SMEM_BH
            + (8 * ((lid >> 3) & 1) + (lid & 7)) * BSTRIDE
            + (wn + 16 * p + 8 * (lid >> 4)) * 2;

    const uint32_t dAL = SMEM_AL - SMEM_AH;
    const uint32_t dBL = SMEM_BL - SMEM_BH;

    #pragma unroll
    for (int ks = 0; ks < 8; ks++) {
        const uint32_t ako = ks * 32;
        const uint32_t bko = ks * 16 * BSTRIDE;

        uint32_t ah[4], al[4];
        ldsm4(ah, aAddr + ako);
        ldsm4(al, aAddr + ako + dAL);

        uint32_t bh[2][4], bl[2][4];
        #pragma unroll
        for (int p = 0; p < 2; p++) {
            ldsm4t(bh[p], bAddr[p] + bko);
            ldsm4t(bl[p], bAddr[p] + bko + dBL);
        }

        #pragma unroll
        for (int nt = 0; nt < 4; nt++) {
            const int p = nt >> 1, q = (nt & 1) * 2;
            mma_bf16(hh[nt], ah, bh[p][q], bh[p][q + 1]);
            mma_bf16(hl[nt], ah, bl[p][q], bl[p][q + 1]);
            mma_bf16(lh[nt], al, bh[p][q], bh[p][q + 1]);
        }
    }

    // ---- epilogue: combine terms, scale, store ----
    #pragma unroll
    for (int nt = 0; nt < 4; nt++) {
        const int r0 = row0 + wm + (lid >> 2);
        const int c  = col0 + wn + 8 * nt + 2 * (lid & 3);
        float v0 = (hh[nt][0] + hl[nt][0] + lh[nt][0]) * s;
        float v1 = (hh[nt][1] + hl[nt][1] + lh[nt][1]) * s;
        float v2 = (hh[nt][2] + hl[nt][2] + lh[nt][2]) * s;
        float v3 = (hh[nt][3] + hl[nt][3] + lh[nt][3]) * s;
        float2 s0 = {v0, v1};
        float2 s1 = {v2, v3};
        *(float2*)&out[(size_t)r0 * NDIM + c]       = s0;
        *(float2*)&out[(size_t)(r0 + 8) * NDIM + c] = s1;
    }
}

extern "C" void kernel_launch(void* const* d_in, const int* in_sizes, int n_in,
                              void* d_out, int out_size) {
    // metadata order: x, adj (UNUSED), W, att (UNUSED), self_weight
    const float* x  = (const float*)d_in[0];
    const float* W  = (const float*)d_in[2];
    const float* sw = (const float*)d_in[4];
    float* out      = (float*)d_out;

    cudaFuncSetAttribute(gat_hmma_kernel,
                         cudaFuncAttributeMaxDynamicSharedMemorySize, SMEM_TOTAL);

    const int M = in_sizes[0] / KDIM;             // 8192
    dim3 grid((M / TM) * (NDIM / TN));            // 128 * 2 = 256 blocks
    gat_hmma_kernel<<<grid, 256, SMEM_TOTAL>>>(x, W, sw, out);
}